// round 2
// baseline (speedup 1.0000x reference)
#include <cuda_runtime.h>
#include <math.h>

// Problem constants
#define BB 2
#define NN 512
#define CC 151
#define DD 4096
#define SCORE_THRESH 0.05f
#define NMS_THRESH 0.5
#define TOPN_PER_CLS 300
#define DET_PER_IMG 100
#define W_CLIP 799.0f
#define H_CLIP 599.0f

// input element counts (for pointer identification)
#define SZ_LOGITS (BB*NN*CC)       // 154624
#define SZ_REG    (BB*NN*CC*4)     // 618496
#define SZ_PROPS  (BB*NN*4)        // 4096
#define SZ_FEATS  (BB*NN*DD)       // 4194304

// output layout (float32)
#define OFF_BOXES  0
#define OFF_SCORES (BB*NN*4)            // 4096
#define OFF_LABELS (OFF_SCORES + BB*NN) // 5120
#define OFF_VALID  (OFF_LABELS + BB*NN) // 6144
#define OFF_FEATS  (OFF_VALID + BB*NN)  // 7168

// scratch (device globals; no allocation allowed)
__device__ float g_prob[BB*CC*NN];   // [b][c][n]
__device__ float g_dist[BB*CC*NN];   // [b][c][n]  kept score or 0
__device__ float g_validf[BB*NN];    // 1.0/0.0 mask for features

// ---------------------------------------------------------------------------
// helpers
// ---------------------------------------------------------------------------
__device__ __forceinline__ void decode_clip(const float* pb, const float* rg,
                                            float& X1, float& Y1, float& X2, float& Y2)
{
    const double DCLAMP = (double)(float)log(62.5);  // float(np.log(1000/16)) as double
    double x1 = pb[0], y1 = pb[1], x2 = pb[2], y2 = pb[3];
    double w = x2 - x1 + 1.0, h = y2 - y1 + 1.0;
    double cx = x1 + 0.5 * w, cy = y1 + 0.5 * h;
    double dx = (double)rg[0] / 10.0;
    double dy = (double)rg[1] / 10.0;
    double dw = fmin((double)rg[2] / 5.0, DCLAMP);
    double dh = fmin((double)rg[3] / 5.0, DCLAMP);
    double pcx = dx * w + cx, pcy = dy * h + cy;
    double pw = exp(dw) * w, ph = exp(dh) * h;
    float a = (float)(pcx - 0.5 * pw);
    float b = (float)(pcy - 0.5 * ph);
    float c = (float)(pcx + 0.5 * pw - 1.0);
    float d = (float)(pcy + 0.5 * ph - 1.0);
    X1 = fminf(fmaxf(a, 0.f), W_CLIP);
    Y1 = fminf(fmaxf(b, 0.f), H_CLIP);
    X2 = fminf(fmaxf(c, 0.f), W_CLIP);
    Y2 = fminf(fmaxf(d, 0.f), H_CLIP);
}

__device__ __forceinline__ double iou_d(float ax1, float ay1, float ax2, float ay2,
                                        float bx1, float by1, float bx2, float by2)
{
    double areaA = ((double)ax2 - (double)ax1 + 1.0) * ((double)ay2 - (double)ay1 + 1.0);
    double areaB = ((double)bx2 - (double)bx1 + 1.0) * ((double)by2 - (double)by1 + 1.0);
    double xx1 = fmax((double)ax1, (double)bx1);
    double yy1 = fmax((double)ay1, (double)by1);
    double xx2 = fmin((double)ax2, (double)bx2);
    double yy2 = fmin((double)ay2, (double)by2);
    double iw = fmax(xx2 - xx1 + 1.0, 0.0);
    double ih = fmax(yy2 - yy1 + 1.0, 0.0);
    double inter = iw * ih;
    return inter / (areaA + areaB - inter);
}

// ---------------------------------------------------------------------------
// K1: softmax per (b,n); store prob transposed [b][c][n]
// ---------------------------------------------------------------------------
__global__ __launch_bounds__(256) void k_softmax(const float* __restrict__ logits)
{
    int row = blockIdx.x;           // b*NN + n
    int b = row >> 9, n = row & 511;
    int c = threadIdx.x;
    __shared__ float sf[256];
    __shared__ double sd[256];

    float x = (c < CC) ? logits[row * CC + c] : -INFINITY;
    sf[c] = x;
    __syncthreads();
    for (int s = 128; s > 0; s >>= 1) {
        if (c < s) sf[c] = fmaxf(sf[c], sf[c + s]);
        __syncthreads();
    }
    float m = sf[0];
    double e = (c < CC) ? exp((double)x - (double)m) : 0.0;
    sd[c] = e;
    __syncthreads();
    for (int s = 128; s > 0; s >>= 1) {
        if (c < s) sd[c] += sd[c + s];
        __syncthreads();
    }
    double sum = sd[0];
    if (c < CC)
        g_prob[((b * CC + c) << 9) + n] = (float)(e / sum);
}

// ---------------------------------------------------------------------------
// K2: per (b,c) NMS on valid-compacted candidates -> g_dist
// ---------------------------------------------------------------------------
__global__ __launch_bounds__(512) void k_nms(const float* __restrict__ reg,
                                             const float* __restrict__ props)
{
    int blk = blockIdx.x;           // b*CC + c
    int b = blk / CC, c = blk % CC;
    int tid = threadIdx.x;

    const float* prow = g_prob + blk * NN;
    float* drow = g_dist + blk * NN;

    float s = prow[tid];
    drow[tid] = 0.f;                // default: not kept
    if (c == 0) return;             // background class dropped entirely

    __shared__ int cnt;
    __shared__ float cs[NN];
    __shared__ int   cn[NN];
    __shared__ float bx1[NN], by1[NN], bx2[NN], by2[NN];
    __shared__ int   ord[NN];
    __shared__ unsigned char keep[NN];

    if (tid == 0) cnt = 0;
    __syncthreads();

    int slot = -1;
    if (s > SCORE_THRESH) slot = atomicAdd(&cnt, 1);
    if (slot >= 0) { cs[slot] = s; cn[slot] = tid; }
    __syncthreads();

    int M = cnt;
    if (M == 0) return;

    if (tid < M) {
        int n = cn[tid];
        const float* pb = props + (b * NN + n) * 4;
        const float* rg = reg + (size_t)(((b * NN + n) * CC) + c) * 4;
        decode_clip(pb, rg, bx1[tid], by1[tid], bx2[tid], by2[tid]);
        keep[tid] = 1;
        ord[tid] = tid;
    }
    int P = 1;
    while (P < M) P <<= 1;
    if (tid >= M && tid < P) { cs[tid] = -INFINITY; cn[tid] = 1 << 30; ord[tid] = tid; }
    __syncthreads();

    // bitonic sort ord: descending score, ascending original index (stable argsort match)
    for (int k = 2; k <= P; k <<= 1) {
        for (int j = k >> 1; j > 0; j >>= 1) {
            if (tid < P) {
                int ixj = tid ^ j;
                if (ixj > tid) {
                    int a = ord[tid], bo = ord[ixj];
                    float sa = cs[a], sb = cs[bo];
                    // a "precedes" bo in final descending order?
                    bool pa = (sa > sb) || (sa == sb && cn[a] < cn[bo]);
                    bool desc = ((tid & k) == 0);
                    bool sw = desc ? !pa : pa;
                    if (sw) { ord[tid] = bo; ord[ixj] = a; }
                }
            }
            __syncthreads();
        }
    }

    // greedy NMS in sorted order
    for (int i = 0; i < M - 1; i++) {
        __syncthreads();
        int oi = ord[i];
        if (!keep[oi]) continue;    // uniform across block (shared value)
        float ax1 = bx1[oi], ay1 = by1[oi], ax2 = bx2[oi], ay2 = by2[oi];
        for (int t = i + 1 + tid; t < M; t += blockDim.x) {
            int ot = ord[t];
            if (!keep[ot]) continue;
            double iou = iou_d(ax1, ay1, ax2, ay2, bx1[ot], by1[ot], bx2[ot], by2[ot]);
            if (iou > NMS_THRESH) keep[ot] = 0;
        }
    }
    __syncthreads();

    // per-class top-300 cap in sorted order
    if (tid == 0) {
        int cum = 0;
        for (int t = 0; t < M; t++) {
            int ot = ord[t];
            if (keep[ot]) { if (++cum > TOPN_PER_CLS) keep[ot] = 0; }
        }
    }
    __syncthreads();

    if (tid < M && keep[tid]) drow[cn[tid]] = cs[tid];
}

// ---------------------------------------------------------------------------
// K3: per image: argmax over classes, top-100 threshold, decode winner box,
//     write boxes/scores/labels/valid outputs
// ---------------------------------------------------------------------------
__global__ __launch_bounds__(512) void k_select(const float* __restrict__ reg,
                                                const float* __restrict__ props,
                                                float* __restrict__ out)
{
    int b = blockIdx.x;
    int n = threadIdx.x;

    float best = 0.f; int lab = 0;
    const float* dbase = g_dist + (size_t)b * CC * NN + n;
    #pragma unroll 4
    for (int c = 1; c < CC; c++) {
        float d = dbase[c * NN];
        if (d > best) { best = d; lab = c; }   // strict > == first-index argmax
    }
    bool v0 = best > 0.f;

    __shared__ float ss[NN];
    __shared__ int cnt;
    if (n == 0) cnt = 0;
    __syncthreads();
    ss[n] = v0 ? best : -1.0f;
    if (v0) atomicAdd(&cnt, 1);
    __syncthreads();

    // bitonic descending sort of 512 floats
    for (int k = 2; k <= NN; k <<= 1) {
        for (int j = k >> 1; j > 0; j >>= 1) {
            int ixj = n ^ j;
            if (ixj > n) {
                float a = ss[n], bb = ss[ixj];
                bool desc = ((n & k) == 0);
                bool sw = desc ? (a < bb) : (a > bb);
                if (sw) { ss[n] = bb; ss[ixj] = a; }
            }
            __syncthreads();
        }
    }
    float kth = ss[DET_PER_IMG - 1];
    float thr = (cnt > DET_PER_IMG) ? kth : -1.0f;
    bool det = v0 && (best >= thr);

    float X1 = 0.f, Y1 = 0.f, X2 = 0.f, Y2 = 0.f, sc = 0.f, lb = 0.f, dv = 0.f;
    if (det) {
        const float* pb = props + (b * NN + n) * 4;
        const float* rg = reg + (size_t)(((b * NN + n) * CC) + lab) * 4;
        decode_clip(pb, rg, X1, Y1, X2, Y2);
        sc = best; lb = (float)lab; dv = 1.f;
    }
    int idx = b * NN + n;
    out[OFF_BOXES + idx * 4 + 0] = X1;
    out[OFF_BOXES + idx * 4 + 1] = Y1;
    out[OFF_BOXES + idx * 4 + 2] = X2;
    out[OFF_BOXES + idx * 4 + 3] = Y2;
    out[OFF_SCORES + idx] = sc;
    out[OFF_LABELS + idx] = lb;
    out[OFF_VALID  + idx] = dv;
    g_validf[idx] = dv;
}

// ---------------------------------------------------------------------------
// K4: features * det_valid  (memory-bound, float4)
// ---------------------------------------------------------------------------
__global__ __launch_bounds__(256) void k_feats(const float4* __restrict__ f,
                                               float4* __restrict__ out)
{
    int i = blockIdx.x * blockDim.x + threadIdx.x;
    if (i >= SZ_FEATS / 4) return;
    float m = g_validf[i >> 10];     // DD/4 = 1024 float4 per row
    float4 v = f[i];
    v.x *= m; v.y *= m; v.z *= m; v.w *= m;
    out[i] = v;
}

// ---------------------------------------------------------------------------
extern "C" void kernel_launch(void* const* d_in, const int* in_sizes, int n_in,
                              void* d_out, int out_size)
{
    const float *logits = nullptr, *reg = nullptr, *props = nullptr, *feats = nullptr;
    for (int i = 0; i < n_in; i++) {
        switch (in_sizes[i]) {
            case SZ_LOGITS: logits = (const float*)d_in[i]; break;
            case SZ_REG:    reg    = (const float*)d_in[i]; break;
            case SZ_PROPS:  props  = (const float*)d_in[i]; break;
            case SZ_FEATS:  feats  = (const float*)d_in[i]; break;
            default: break;
        }
    }
    float* out = (float*)d_out;

    k_softmax<<<BB * NN, 256>>>(logits);
    k_nms<<<BB * CC, 512>>>(reg, props);
    k_select<<<BB, 512>>>(reg, props, out);
    k_feats<<<(SZ_FEATS / 4 + 255) / 256, 256>>>((const float4*)feats,
                                                 (float4*)(out + OFF_FEATS));
    (void)out_size;
}

// round 3
// speedup vs baseline: 1.1019x; 1.1019x over previous
#include <cuda_runtime.h>
#include <math.h>

// Problem constants
#define BB 2
#define NN 512
#define CC 151
#define DD 4096
#define SCORE_THRESH 0.05f
#define NMS_THRESH 0.5
#define TOPN_PER_CLS 300
#define DET_PER_IMG 100
#define W_CLIP 799.0f
#define H_CLIP 599.0f

// input element counts (for pointer identification)
#define SZ_LOGITS (BB*NN*CC)       // 154624
#define SZ_REG    (BB*NN*CC*4)     // 618496
#define SZ_PROPS  (BB*NN*4)        // 4096
#define SZ_FEATS  (BB*NN*DD)       // 4194304

// output layout (float32)
#define OFF_BOXES  0
#define OFF_SCORES (BB*NN*4)            // 4096
#define OFF_LABELS (OFF_SCORES + BB*NN) // 5120
#define OFF_VALID  (OFF_LABELS + BB*NN) // 6144
#define OFF_FEATS  (OFF_VALID + BB*NN)  // 7168

// scratch (device globals; no allocation allowed)
__device__ float g_prob[BB*CC*NN];   // [b][c][n]
__device__ float g_dist[BB*CC*NN];   // [b][c][n]  kept score or 0
__device__ float g_validf[BB*NN];    // 1.0/0.0 mask for features

// ---------------------------------------------------------------------------
// helpers (decode/IoU stay double: decision-critical geometry, ~2K calls only)
// ---------------------------------------------------------------------------
__device__ __forceinline__ void decode_clip(const float* pb, const float* rg,
                                            float& X1, float& Y1, float& X2, float& Y2)
{
    const double DCLAMP = (double)(float)log(62.5);  // float(np.log(1000/16)) as double
    double x1 = pb[0], y1 = pb[1], x2 = pb[2], y2 = pb[3];
    double w = x2 - x1 + 1.0, h = y2 - y1 + 1.0;
    double cx = x1 + 0.5 * w, cy = y1 + 0.5 * h;
    double dx = (double)rg[0] / 10.0;
    double dy = (double)rg[1] / 10.0;
    double dw = fmin((double)rg[2] / 5.0, DCLAMP);
    double dh = fmin((double)rg[3] / 5.0, DCLAMP);
    double pcx = dx * w + cx, pcy = dy * h + cy;
    double pw = exp(dw) * w, ph = exp(dh) * h;
    float a = (float)(pcx - 0.5 * pw);
    float b = (float)(pcy - 0.5 * ph);
    float c = (float)(pcx + 0.5 * pw - 1.0);
    float d = (float)(pcy + 0.5 * ph - 1.0);
    X1 = fminf(fmaxf(a, 0.f), W_CLIP);
    Y1 = fminf(fmaxf(b, 0.f), H_CLIP);
    X2 = fminf(fmaxf(c, 0.f), W_CLIP);
    Y2 = fminf(fmaxf(d, 0.f), H_CLIP);
}

__device__ __forceinline__ double iou_d(float ax1, float ay1, float ax2, float ay2,
                                        float bx1, float by1, float bx2, float by2)
{
    double areaA = ((double)ax2 - (double)ax1 + 1.0) * ((double)ay2 - (double)ay1 + 1.0);
    double areaB = ((double)bx2 - (double)bx1 + 1.0) * ((double)by2 - (double)by1 + 1.0);
    double xx1 = fmax((double)ax1, (double)bx1);
    double yy1 = fmax((double)ay1, (double)by1);
    double xx2 = fmin((double)ax2, (double)bx2);
    double yy2 = fmin((double)ay2, (double)by2);
    double iw = fmax(xx2 - xx1 + 1.0, 0.0);
    double ih = fmax(yy2 - yy1 + 1.0, 0.0);
    double inter = iw * ih;
    return inter / (areaA + areaB - inter);
}

// ---------------------------------------------------------------------------
// K1: softmax per (b,n) in fp32; store prob transposed [b][c][n]
// ---------------------------------------------------------------------------
__global__ __launch_bounds__(256) void k_softmax(const float* __restrict__ logits)
{
    int row = blockIdx.x;           // b*NN + n
    int b = row >> 9, n = row & 511;
    int c = threadIdx.x;
    __shared__ float sf[256];

    float x = (c < CC) ? logits[row * CC + c] : -INFINITY;
    sf[c] = x;
    __syncthreads();
    for (int s = 128; s > 0; s >>= 1) {
        if (c < s) sf[c] = fmaxf(sf[c], sf[c + s]);
        __syncthreads();
    }
    float m = sf[0];
    __syncthreads();
    float e = (c < CC) ? expf(x - m) : 0.0f;
    sf[c] = e;
    __syncthreads();
    for (int s = 128; s > 0; s >>= 1) {
        if (c < s) sf[c] += sf[c + s];
        __syncthreads();
    }
    float sum = sf[0];
    if (c < CC)
        g_prob[((b * CC + c) << 9) + n] = e / sum;
}

// ---------------------------------------------------------------------------
// K2: per (b,c) NMS on valid-compacted candidates -> g_dist
// ---------------------------------------------------------------------------
__global__ __launch_bounds__(512) void k_nms(const float* __restrict__ reg,
                                             const float* __restrict__ props)
{
    int blk = blockIdx.x;           // b*CC + c
    int b = blk / CC, c = blk % CC;
    int tid = threadIdx.x;

    const float* prow = g_prob + blk * NN;
    float* drow = g_dist + blk * NN;

    float s = prow[tid];
    drow[tid] = 0.f;                // default: not kept
    if (c == 0) return;             // background class dropped entirely

    __shared__ int cnt;
    __shared__ float cs[NN];
    __shared__ int   cn[NN];
    __shared__ float bx1[NN], by1[NN], bx2[NN], by2[NN];
    __shared__ int   ord[NN];
    __shared__ unsigned char keep[NN];

    if (tid == 0) cnt = 0;
    __syncthreads();

    int slot = -1;
    if (s > SCORE_THRESH) slot = atomicAdd(&cnt, 1);
    if (slot >= 0) { cs[slot] = s; cn[slot] = tid; }
    __syncthreads();

    int M = cnt;
    if (M == 0) return;

    if (tid < M) {
        int n = cn[tid];
        const float* pb = props + (b * NN + n) * 4;
        const float* rg = reg + (size_t)(((b * NN + n) * CC) + c) * 4;
        decode_clip(pb, rg, bx1[tid], by1[tid], bx2[tid], by2[tid]);
        keep[tid] = 1;
        ord[tid] = tid;
    }
    int P = 1;
    while (P < M) P <<= 1;
    if (tid >= M && tid < P) { cs[tid] = -INFINITY; cn[tid] = 1 << 30; ord[tid] = tid; }
    __syncthreads();

    // bitonic sort ord: descending score, ascending original index (stable argsort match)
    for (int k = 2; k <= P; k <<= 1) {
        for (int j = k >> 1; j > 0; j >>= 1) {
            if (tid < P) {
                int ixj = tid ^ j;
                if (ixj > tid) {
                    int a = ord[tid], bo = ord[ixj];
                    float sa = cs[a], sb = cs[bo];
                    bool pa = (sa > sb) || (sa == sb && cn[a] < cn[bo]);
                    bool desc = ((tid & k) == 0);
                    bool sw = desc ? !pa : pa;
                    if (sw) { ord[tid] = bo; ord[ixj] = a; }
                }
            }
            __syncthreads();
        }
    }

    // greedy NMS in sorted order
    for (int i = 0; i < M - 1; i++) {
        __syncthreads();
        int oi = ord[i];
        if (!keep[oi]) continue;    // uniform across block (shared value)
        float ax1 = bx1[oi], ay1 = by1[oi], ax2 = bx2[oi], ay2 = by2[oi];
        for (int t = i + 1 + tid; t < M; t += blockDim.x) {
            int ot = ord[t];
            if (!keep[ot]) continue;
            double iou = iou_d(ax1, ay1, ax2, ay2, bx1[ot], by1[ot], bx2[ot], by2[ot]);
            if (iou > NMS_THRESH) keep[ot] = 0;
        }
    }
    __syncthreads();

    // per-class top-300 cap in sorted order
    if (tid == 0) {
        int cum = 0;
        for (int t = 0; t < M; t++) {
            int ot = ord[t];
            if (keep[ot]) { if (++cum > TOPN_PER_CLS) keep[ot] = 0; }
        }
    }
    __syncthreads();

    if (tid < M && keep[tid]) drow[cn[tid]] = cs[tid];
}

// ---------------------------------------------------------------------------
// K3: per image: argmax over classes, top-100 threshold, decode winner box,
//     write boxes/scores/labels/valid outputs
// ---------------------------------------------------------------------------
__global__ __launch_bounds__(512) void k_select(const float* __restrict__ reg,
                                                const float* __restrict__ props,
                                                float* __restrict__ out)
{
    int b = blockIdx.x;
    int n = threadIdx.x;

    float best = 0.f; int lab = 0;
    const float* dbase = g_dist + (size_t)b * CC * NN + n;
    #pragma unroll 4
    for (int c = 1; c < CC; c++) {
        float d = dbase[c * NN];
        if (d > best) { best = d; lab = c; }   // strict > == first-index argmax
    }
    bool v0 = best > 0.f;

    __shared__ float ss[NN];
    __shared__ int cnt;
    if (n == 0) cnt = 0;
    __syncthreads();
    ss[n] = v0 ? best : -1.0f;
    if (v0) atomicAdd(&cnt, 1);
    __syncthreads();

    // bitonic descending sort of 512 floats
    for (int k = 2; k <= NN; k <<= 1) {
        for (int j = k >> 1; j > 0; j >>= 1) {
            int ixj = n ^ j;
            if (ixj > n) {
                float a = ss[n], bb = ss[ixj];
                bool desc = ((n & k) == 0);
                bool sw = desc ? (a < bb) : (a > bb);
                if (sw) { ss[n] = bb; ss[ixj] = a; }
            }
            __syncthreads();
        }
    }
    float kth = ss[DET_PER_IMG - 1];
    float thr = (cnt > DET_PER_IMG) ? kth : -1.0f;
    bool det = v0 && (best >= thr);

    float X1 = 0.f, Y1 = 0.f, X2 = 0.f, Y2 = 0.f, sc = 0.f, lb = 0.f, dv = 0.f;
    if (det) {
        const float* pb = props + (b * NN + n) * 4;
        const float* rg = reg + (size_t)(((b * NN + n) * CC) + lab) * 4;
        decode_clip(pb, rg, X1, Y1, X2, Y2);
        sc = best; lb = (float)lab; dv = 1.f;
    }
    int idx = b * NN + n;
    out[OFF_BOXES + idx * 4 + 0] = X1;
    out[OFF_BOXES + idx * 4 + 1] = Y1;
    out[OFF_BOXES + idx * 4 + 2] = X2;
    out[OFF_BOXES + idx * 4 + 3] = Y2;
    out[OFF_SCORES + idx] = sc;
    out[OFF_LABELS + idx] = lb;
    out[OFF_VALID  + idx] = dv;
    g_validf[idx] = dv;
}

// ---------------------------------------------------------------------------
// K4: features * det_valid  (memory-bound, float4, ILP=4)
// ---------------------------------------------------------------------------
#define F4_TOTAL (SZ_FEATS / 4)           // 1048576 float4
#define F4_PER_THREAD 4
#define F4_THREADS (F4_TOTAL / F4_PER_THREAD)  // 262144

__global__ __launch_bounds__(256) void k_feats(const float4* __restrict__ f,
                                               float4* __restrict__ out)
{
    int t = blockIdx.x * blockDim.x + threadIdx.x;
    #pragma unroll
    for (int j = 0; j < F4_PER_THREAD; j++) {
        int i = t + j * F4_THREADS;
        float m = g_validf[i >> 10];     // DD/4 = 1024 float4 per row
        float4 v = f[i];
        v.x *= m; v.y *= m; v.z *= m; v.w *= m;
        out[i] = v;
    }
}

// ---------------------------------------------------------------------------
extern "C" void kernel_launch(void* const* d_in, const int* in_sizes, int n_in,
                              void* d_out, int out_size)
{
    const float *logits = nullptr, *reg = nullptr, *props = nullptr, *feats = nullptr;
    for (int i = 0; i < n_in; i++) {
        switch (in_sizes[i]) {
            case SZ_LOGITS: logits = (const float*)d_in[i]; break;
            case SZ_REG:    reg    = (const float*)d_in[i]; break;
            case SZ_PROPS:  props  = (const float*)d_in[i]; break;
            case SZ_FEATS:  feats  = (const float*)d_in[i]; break;
            default: break;
        }
    }
    float* out = (float*)d_out;

    k_softmax<<<BB * NN, 256>>>(logits);
    k_nms<<<BB * CC, 512>>>(reg, props);
    k_select<<<BB, 512>>>(reg, props, out);
    k_feats<<<F4_THREADS / 256, 256>>>((const float4*)feats,
                                       (float4*)(out + OFF_FEATS));
    (void)out_size;
}